// round 6
// baseline (speedup 1.0000x reference)
#include <cuda_runtime.h>
#include <math.h>
#include <stdint.h>

// Problem constants
constexpr int Bc  = 2;
constexpr int Sc  = 2048;
constexpr int Dc  = 1024;
constexpr int Hc  = 16;
constexpr int HDc = 64;
constexpr int Mc  = Bc * Sc;          // 4096 rows for projections

// ---------------------------------------------------------------------------
// Device scratch (allocations forbidden; use __device__ globals)
// ---------------------------------------------------------------------------
__device__ float g_q[(size_t)Bc * Sc * Dc];
__device__ float g_k[(size_t)Bc * Sc * Dc];
__device__ float g_v[(size_t)Bc * Sc * Dc];
__device__ float g_ctx[(size_t)Bc * Sc * Dc];

// ---------------------------------------------------------------------------
// Helpers
// ---------------------------------------------------------------------------
__device__ __forceinline__ uint32_t f2tf32(float f) {
    uint32_t u;
    asm("cvt.rna.tf32.f32 %0, %1;" : "=r"(u) : "f"(f));
    return u;
}
__device__ __forceinline__ float f2tf32f(float f) {
    return __uint_as_float(f2tf32(f));
}

// D += A(16x8) * B(8x8)  (m16n8k8 row.col, tf32)
__device__ __forceinline__ void mma_tf32(float* d, const uint32_t* a, const uint32_t* b) {
    asm volatile(
        "mma.sync.aligned.m16n8k8.row.col.f32.tf32.tf32.f32 "
        "{%0,%1,%2,%3}, {%4,%5,%6,%7}, {%8,%9}, {%0,%1,%2,%3};"
        : "+f"(d[0]), "+f"(d[1]), "+f"(d[2]), "+f"(d[3])
        : "r"(a[0]), "r"(a[1]), "r"(a[2]), "r"(a[3]), "r"(b[0]), "r"(b[1]));
}

// ---------------------------------------------------------------------------
// tf32 GEMM v2 (NT), 3 problems via blockIdx.z:
//   Cz[m,n] = sum_k A[m,k] * Wz[n,k] + bz[n]
// BM=BN=128, BK=16, 256 threads = 8 warps (2m x 4n), warp tile 64x32.
// Double-buffered smem. Paired-column layout: within each k8 group the
// element order is [k0,k4,k1,k5,k2,k6,k3,k7] so a B fragment is one LDS.64
// and an A fragment is two LDS.64, all bank-conflict-free (stride 24).
// RNA tf32 rounding applied on the smem fill path.
// ---------------------------------------------------------------------------
constexpr int GLD = 24;   // smem row stride (floats)

__global__ __launch_bounds__(256, 2) void gemm3_v2(
    const float* __restrict__ A,
    const float* __restrict__ W0, const float* __restrict__ b0, float* __restrict__ C0,
    const float* __restrict__ W1, const float* __restrict__ b1, float* __restrict__ C1,
    const float* __restrict__ W2, const float* __restrict__ b2, float* __restrict__ C2)
{
    const int z = blockIdx.z;
    const float* B    = (z == 0) ? W0 : (z == 1) ? W1 : W2;
    const float* bias = (z == 0) ? b0 : (z == 1) ? b1 : b2;
    float*       C    = (z == 0) ? C0 : (z == 1) ? C1 : C2;

    __shared__ float As[2][128 * GLD];
    __shared__ float Bs[2][128 * GLD];

    const int tid  = threadIdx.x;
    const int lane = tid & 31;
    const int warp = tid >> 5;
    const int wm   = warp >> 2;          // 0..1
    const int wn   = warp & 3;           // 0..3
    const int g    = lane >> 2;          // 0..7
    const int t    = lane & 3;           // 0..3
    const int bm   = blockIdx.y * 128;
    const int bn   = blockIdx.x * 128;

    // fill: each thread owns one 8-column group of one row (A and B)
    const int fr = tid >> 1;             // 0..127
    const int fq = tid & 1;              // 0..1
    const float* Ag = A + (size_t)(bm + fr) * Dc + fq * 8;
    const float* Bg = B + (size_t)(bn + fr) * Dc + fq * 8;
    float* asp = &As[0][0] + fr * GLD + fq * 8;
    float* bsp = &Bs[0][0] + fr * GLD + fq * 8;
    const int bufStride = 128 * GLD;

    float acc[4][4][4];
#pragma unroll
    for (int mt = 0; mt < 4; mt++)
#pragma unroll
        for (int nt = 0; nt < 4; nt++)
#pragma unroll
            for (int i = 0; i < 4; i++) acc[mt][nt][i] = 0.f;

    float4 a0, a1, bb0, bb1;
    a0  = *(const float4*)(Ag + 0);
    a1  = *(const float4*)(Ag + 4);
    bb0 = *(const float4*)(Bg + 0);
    bb1 = *(const float4*)(Bg + 4);

    // store paired + RNA-rounded: smem order [k0,k4,k1,k5,k2,k6,k3,k7]
    *(float4*)(asp + 0) = make_float4(f2tf32f(a0.x), f2tf32f(a1.x), f2tf32f(a0.y), f2tf32f(a1.y));
    *(float4*)(asp + 4) = make_float4(f2tf32f(a0.z), f2tf32f(a1.z), f2tf32f(a0.w), f2tf32f(a1.w));
    *(float4*)(bsp + 0) = make_float4(f2tf32f(bb0.x), f2tf32f(bb1.x), f2tf32f(bb0.y), f2tf32f(bb1.y));
    *(float4*)(bsp + 4) = make_float4(f2tf32f(bb0.z), f2tf32f(bb1.z), f2tf32f(bb0.w), f2tf32f(bb1.w));
    __syncthreads();

    const int aRow0 = (wm * 64 + g) * GLD + 2 * t;   // + mt*16*GLD + ks*8
    const int bRow0 = (wn * 32 + g) * GLD + 2 * t;   // + nt*8*GLD  + ks*8

    for (int it = 0; it < Dc / 16; it++) {
        const int cur = it & 1;

        if (it + 1 < Dc / 16) {
            const int k = (it + 1) * 16;
            a0  = *(const float4*)(Ag + k + 0);
            a1  = *(const float4*)(Ag + k + 4);
            bb0 = *(const float4*)(Bg + k + 0);
            bb1 = *(const float4*)(Bg + k + 4);
        }

        const float* Ab = &As[cur][0];
        const float* Bb = &Bs[cur][0];
#pragma unroll
        for (int ks = 0; ks < 2; ks++) {
            uint2 a02[4], a13[4], bf[4];
#pragma unroll
            for (int mt = 0; mt < 4; mt++) {
                const int base = aRow0 + mt * 16 * GLD + ks * 8;
                a02[mt] = *(const uint2*)(Ab + base);
                a13[mt] = *(const uint2*)(Ab + base + 8 * GLD);
            }
#pragma unroll
            for (int nt = 0; nt < 4; nt++)
                bf[nt] = *(const uint2*)(Bb + bRow0 + nt * 8 * GLD + ks * 8);
#pragma unroll
            for (int mt = 0; mt < 4; mt++) {
                uint32_t af[4] = { a02[mt].x, a13[mt].x, a02[mt].y, a13[mt].y };
#pragma unroll
                for (int nt = 0; nt < 4; nt++) {
                    uint32_t bb[2] = { bf[nt].x, bf[nt].y };
                    mma_tf32(acc[mt][nt], af, bb);
                }
            }
        }

        if (it + 1 < Dc / 16) {
            float* ad = asp + (cur ^ 1) * bufStride;
            float* bd = bsp + (cur ^ 1) * bufStride;
            *(float4*)(ad + 0) = make_float4(f2tf32f(a0.x), f2tf32f(a1.x), f2tf32f(a0.y), f2tf32f(a1.y));
            *(float4*)(ad + 4) = make_float4(f2tf32f(a0.z), f2tf32f(a1.z), f2tf32f(a0.w), f2tf32f(a1.w));
            *(float4*)(bd + 0) = make_float4(f2tf32f(bb0.x), f2tf32f(bb1.x), f2tf32f(bb0.y), f2tf32f(bb1.y));
            *(float4*)(bd + 4) = make_float4(f2tf32f(bb0.z), f2tf32f(bb1.z), f2tf32f(bb0.w), f2tf32f(bb1.w));
        }
        __syncthreads();
    }

    // epilogue
#pragma unroll
    for (int mt = 0; mt < 4; mt++) {
        const int row = bm + wm * 64 + mt * 16 + g;
#pragma unroll
        for (int nt = 0; nt < 4; nt++) {
            const int col = bn + wn * 32 + nt * 8 + 2 * t;
            const float2 bv = *(const float2*)(bias + col);
            *(float2*)(C + (size_t)row * Dc + col) =
                make_float2(acc[mt][nt][0] + bv.x, acc[mt][nt][1] + bv.y);
            *(float2*)(C + (size_t)(row + 8) * Dc + col) =
                make_float2(acc[mt][nt][2] + bv.x, acc[mt][nt][3] + bv.y);
        }
    }
}

// ---------------------------------------------------------------------------
// Flash attention v3 (RNA-rounded), single pass, no max subtraction:
//   per tile: S = Q@K^T (mma) -> E = exp(S) -> write E to attn, accumulate
//   Z partials, shuffle E to A-fragments (RNA), ctx += E@V.
//   Epilogue: reduce Z, write ctx*invZ, rescale own attn strip by invZ
//   (mostly L2-resident; replaces the separate normalize kernel).
// K tile paired-column (B frag = 1 LDS.64, CF), V tile straight (CF).
// ---------------------------------------------------------------------------
constexpr int AT_Q = 64;     // q rows per block (4 warps x 16 rows)
constexpr int K_LD = 72;
constexpr int V_LD = 72;

__global__ __launch_bounds__(128, 4) void attention_flash3_kernel(float* __restrict__ attn)
{
    __shared__ float Ks[64 * K_LD];
    __shared__ float Vs[64 * V_LD];
    __shared__ float invZs[AT_Q];

    const int tid  = threadIdx.x;
    const int lane = tid & 31;
    const int warp = tid >> 5;           // 0..3
    const int g    = lane >> 2;          // 0..7
    const int t    = lane & 3;           // 0..3

    const int qt = blockIdx.x;           // 0..31
    const int h  = blockIdx.y;
    const int b  = blockIdx.z;

    const float* Qg = g_q + (size_t)b * Sc * Dc + h * HDc;
    const float* Kg = g_k + (size_t)b * Sc * Dc + h * HDc;
    const float* Vg = g_v + (size_t)b * Sc * Dc + h * HDc;

    const int qrow = qt * AT_Q + warp * 16 + g;

    // ---- Q fragments in registers, scaled by 1/8, RNA tf32 ----
    uint32_t qf[8][4];
#pragma unroll
    for (int ks = 0; ks < 8; ks++) {
        const float* q0 = Qg + (size_t)qrow * Dc + ks * 8;
        const float* q1 = Qg + (size_t)(qrow + 8) * Dc + ks * 8;
        qf[ks][0] = f2tf32(q0[t    ] * 0.125f);
        qf[ks][1] = f2tf32(q1[t    ] * 0.125f);
        qf[ks][2] = f2tf32(q0[t + 4] * 0.125f);
        qf[ks][3] = f2tf32(q1[t + 4] * 0.125f);
    }

    float ctx[8][4];
#pragma unroll
    for (int nt = 0; nt < 8; nt++)
#pragma unroll
        for (int i = 0; i < 4; i++) ctx[nt][i] = 0.f;

    float Z0 = 0.f, Z1 = 0.f;

    float* awr0 = attn + ((size_t)(b * Hc + h) * Sc + qrow) * Sc;
    float* awr1 = awr0 + (size_t)8 * Sc;

    for (int kt = 0; kt < Sc / 64; kt++) {
        // ---- K tile fill: paired columns, RNA, vectorized ----
#pragma unroll
        for (int i = 0; i < 4; i++) {
            const int f = tid + i * 128;       // 0..511 group slots
            const int r = f >> 3;              // 0..63
            const int q = f & 7;               // k8 group
            const float* src = Kg + (size_t)(kt * 64 + r) * Dc + q * 8;
            const float4 v0 = *(const float4*)(src + 0);
            const float4 v1 = *(const float4*)(src + 4);
            float* dst = Ks + r * K_LD + q * 8;
            *(float4*)(dst + 0) = make_float4(f2tf32f(v0.x), f2tf32f(v1.x), f2tf32f(v0.y), f2tf32f(v1.y));
            *(float4*)(dst + 4) = make_float4(f2tf32f(v0.z), f2tf32f(v1.z), f2tf32f(v0.w), f2tf32f(v1.w));
        }
        // ---- V tile fill: straight layout, RNA ----
#pragma unroll
        for (int i = 0; i < 8; i++) {
            const int f  = tid + i * 128;
            const int r  = f >> 4;
            const int c4 = (f & 15) * 4;
            const float4 v = *(const float4*)(Vg + (size_t)(kt * 64 + r) * Dc + c4);
            *(float4*)(Vs + r * V_LD + c4) =
                make_float4(f2tf32f(v.x), f2tf32f(v.y), f2tf32f(v.z), f2tf32f(v.w));
        }
        __syncthreads();

        // ---- S = Q @ K^T ----
        float sacc[8][4];
#pragma unroll
        for (int nt = 0; nt < 8; nt++)
#pragma unroll
            for (int i = 0; i < 4; i++) sacc[nt][i] = 0.f;

#pragma unroll
        for (int ks = 0; ks < 8; ks++) {
#pragma unroll
            for (int nt = 0; nt < 8; nt++) {
                const uint2 kp = *(const uint2*)(Ks + (nt * 8 + g) * K_LD + ks * 8 + 2 * t);
                uint32_t bf[2] = { kp.x, kp.y };
                mma_tf32(sacc[nt], qf[ks], bf);
            }
        }

        // ---- E = exp(S); Z partials; write E ----
#pragma unroll
        for (int nt = 0; nt < 8; nt++) {
            sacc[nt][0] = __expf(sacc[nt][0]);
            sacc[nt][1] = __expf(sacc[nt][1]);
            sacc[nt][2] = __expf(sacc[nt][2]);
            sacc[nt][3] = __expf(sacc[nt][3]);
            Z0 += sacc[nt][0] + sacc[nt][1];
            Z1 += sacc[nt][2] + sacc[nt][3];
            const int col = kt * 64 + nt * 8 + 2 * t;
            *(float2*)(awr0 + col) = make_float2(sacc[nt][0], sacc[nt][1]);
            *(float2*)(awr1 + col) = make_float2(sacc[nt][2], sacc[nt][3]);
        }

        // ---- ctx += E @ V (accumulator -> A fragment via shuffles, RNA) ----
        const int srcA = (lane & ~3) | (t >> 1);
        const bool odd = (t & 1);
#pragma unroll
        for (int j = 0; j < 8; j++) {
            const float e0 = __shfl_sync(0xffffffff, sacc[j][0], srcA);
            const float o0 = __shfl_sync(0xffffffff, sacc[j][1], srcA);
            const float e2 = __shfl_sync(0xffffffff, sacc[j][0], srcA + 2);
            const float o2 = __shfl_sync(0xffffffff, sacc[j][1], srcA + 2);
            const float e1 = __shfl_sync(0xffffffff, sacc[j][2], srcA);
            const float o1 = __shfl_sync(0xffffffff, sacc[j][3], srcA);
            const float e3 = __shfl_sync(0xffffffff, sacc[j][2], srcA + 2);
            const float o3 = __shfl_sync(0xffffffff, sacc[j][3], srcA + 2);
            uint32_t af[4];
            af[0] = f2tf32(odd ? o0 : e0);
            af[1] = f2tf32(odd ? o1 : e1);
            af[2] = f2tf32(odd ? o2 : e2);
            af[3] = f2tf32(odd ? o3 : e3);
#pragma unroll
            for (int nt = 0; nt < 8; nt++) {
                uint32_t bf[2];
                bf[0] = __float_as_uint(Vs[(j * 8 + t    ) * V_LD + nt * 8 + g]);
                bf[1] = __float_as_uint(Vs[(j * 8 + t + 4) * V_LD + nt * 8 + g]);
                mma_tf32(ctx[nt], af, bf);
            }
        }
        __syncthreads();   // before next tile overwrites Ks/Vs
    }

    // ---- reduce Z across t-lanes (once) ----
    Z0 += __shfl_xor_sync(0xffffffff, Z0, 1);
    Z0 += __shfl_xor_sync(0xffffffff, Z0, 2);
    Z1 += __shfl_xor_sync(0xffffffff, Z1, 1);
    Z1 += __shfl_xor_sync(0xffffffff, Z1, 2);
    const float invZ0 = 1.0f / Z0;
    const float invZ1 = 1.0f / Z1;

    // ---- write normalized ctx ----
    float* c0 = g_ctx + (size_t)(b * Sc + qrow) * Dc + h * HDc;
    float* c1 = c0 + (size_t)8 * Dc;
#pragma unroll
    for (int nt = 0; nt < 8; nt++) {
        const int col = nt * 8 + 2 * t;
        *(float2*)(c0 + col) = make_float2(ctx[nt][0] * invZ0, ctx[nt][1] * invZ0);
        *(float2*)(c1 + col) = make_float2(ctx[nt][2] * invZ1, ctx[nt][3] * invZ1);
    }

    // ---- in-block normalize of own strip (mostly L2-resident) ----
    if (t == 0) {
        invZs[warp * 16 + g]     = invZ0;
        invZs[warp * 16 + g + 8] = invZ1;
    }
    __syncthreads();

    float* strip = attn + ((size_t)(b * Hc + h) * Sc + (size_t)qt * AT_Q) * Sc;
    for (int r = 0; r < AT_Q; r++) {
        const float iz = invZs[r];
        float* rp = strip + (size_t)r * Sc;
#pragma unroll
        for (int i = 0; i < 4; i++) {
            const int c = (tid + i * 128) * 4;
            float4 v = *(const float4*)(rp + c);
            v.x *= iz;  v.y *= iz;  v.z *= iz;  v.w *= iz;
            *(float4*)(rp + c) = v;
        }
    }
}

// ---------------------------------------------------------------------------
// kernel_launch
//   d_in: x, Wq, bq, Wk, bk, Wv, bv, Wo, bo   (all fp32)
//   d_out: [ out (B*S*D) | attention_weights (B*H*S*S) ]  fp32
// ---------------------------------------------------------------------------
extern "C" void kernel_launch(void* const* d_in, const int* in_sizes, int n_in,
                              void* d_out, int out_size)
{
    (void)in_sizes; (void)n_in; (void)out_size;
    const float* x  = (const float*)d_in[0];
    const float* Wq = (const float*)d_in[1];
    const float* bq = (const float*)d_in[2];
    const float* Wk = (const float*)d_in[3];
    const float* bk = (const float*)d_in[4];
    const float* Wv = (const float*)d_in[5];
    const float* bv = (const float*)d_in[6];
    const float* Wo = (const float*)d_in[7];
    const float* bo = (const float*)d_in[8];

    float* out  = (float*)d_out;
    float* attn = out + (size_t)Bc * Sc * Dc;

    float* gq;  cudaGetSymbolAddress((void**)&gq,  g_q);
    float* gk;  cudaGetSymbolAddress((void**)&gk,  g_k);
    float* gv;  cudaGetSymbolAddress((void**)&gv,  g_v);
    float* gc;  cudaGetSymbolAddress((void**)&gc,  g_ctx);

    dim3 gemmBlock(256);

    // Q/K/V projections fused into one launch
    dim3 qkvGrid(Dc / 128, Mc / 128, 3);     // (8, 32, 3)
    gemm3_v2<<<qkvGrid, gemmBlock>>>(
        x, Wq, bq, gq, Wk, bk, gk, Wv, bv, gv);

    // Flash attention: normalized weights + ctx (normalize fused in epilogue)
    dim3 attnGrid(Sc / AT_Q, Hc, Bc);        // (32, 16, 2)
    attention_flash3_kernel<<<attnGrid, 128>>>(attn);

    // Output projection
    dim3 oGrid(Dc / 128, Mc / 128, 1);       // (8, 32, 1)
    gemm3_v2<<<oGrid, gemmBlock>>>(
        gc, Wo, bo, out, Wo, bo, out, Wo, bo, out);
}

// round 8
// speedup vs baseline: 1.1039x; 1.1039x over previous
#include <cuda_runtime.h>
#include <math.h>
#include <stdint.h>

// Problem constants
constexpr int Bc  = 2;
constexpr int Sc  = 2048;
constexpr int Dc  = 1024;
constexpr int Hc  = 16;
constexpr int HDc = 64;
constexpr int Mc  = Bc * Sc;          // 4096 rows for projections

// ---------------------------------------------------------------------------
// Device scratch (allocations forbidden; use __device__ globals)
// ---------------------------------------------------------------------------
__device__ float g_q[(size_t)Bc * Sc * Dc];
__device__ float g_k[(size_t)Bc * Sc * Dc];
__device__ float g_v[(size_t)Bc * Sc * Dc];
__device__ float g_ctx[(size_t)Bc * Sc * Dc];

// ---------------------------------------------------------------------------
// Helpers
// ---------------------------------------------------------------------------
__device__ __forceinline__ uint32_t f2tf32(float f) {
    uint32_t u;
    asm("cvt.rna.tf32.f32 %0, %1;" : "=r"(u) : "f"(f));
    return u;
}
__device__ __forceinline__ float f2tf32f(float f) {
    return __uint_as_float(f2tf32(f));
}

// D += A(16x8, tf32) * B(8x8, tf32)   (m16n8k8, row.col)
__device__ __forceinline__ void mma_tf32(float* d, const uint32_t* a, const uint32_t* b) {
    asm volatile(
        "mma.sync.aligned.m16n8k8.row.col.f32.tf32.tf32.f32 "
        "{%0,%1,%2,%3}, {%4,%5,%6,%7}, {%8,%9}, {%0,%1,%2,%3};"
        : "+f"(d[0]), "+f"(d[1]), "+f"(d[2]), "+f"(d[3])
        : "r"(a[0]), "r"(a[1]), "r"(a[2]), "r"(a[3]), "r"(b[0]), "r"(b[1]));
}

// ---------------------------------------------------------------------------
// tf32 GEMM (NT), 3 problems fused via blockIdx.z (R3-proven version):
//   Cz[m,n] = sum_k A[m,k] * Wz[n,k] + bz[n]
// BM=128, BN=64, BK=32, 256 threads = 8 warps (4m x 2n), warp tile 32x32.
// ---------------------------------------------------------------------------
__global__ __launch_bounds__(256) void gemm3_tf32_nt_bias(
    const float* __restrict__ A,
    const float* __restrict__ W0, const float* __restrict__ b0, float* __restrict__ C0,
    const float* __restrict__ W1, const float* __restrict__ b1, float* __restrict__ C1,
    const float* __restrict__ W2, const float* __restrict__ b2, float* __restrict__ C2,
    int M, int N, int K)
{
    const int z = blockIdx.z;
    const float* B    = (z == 0) ? W0 : (z == 1) ? W1 : W2;
    const float* bias = (z == 0) ? b0 : (z == 1) ? b1 : b2;
    float*       C    = (z == 0) ? C0 : (z == 1) ? C1 : C2;

    __shared__ float As[128][36];
    __shared__ float Bs[64][36];

    const int tid  = threadIdx.x;
    const int lane = tid & 31;
    const int warp = tid >> 5;
    const int wm   = warp >> 1;          // 0..3
    const int wn   = warp & 1;           // 0..1
    const int g    = lane >> 2;          // 0..7
    const int t    = lane & 3;           // 0..3
    const int bm   = blockIdx.y * 128;
    const int bn   = blockIdx.x * 64;

    float acc[2][4][4];
#pragma unroll
    for (int mt = 0; mt < 2; mt++)
#pragma unroll
        for (int nt = 0; nt < 4; nt++)
#pragma unroll
            for (int i = 0; i < 4; i++) acc[mt][nt][i] = 0.f;

    float4 aReg[4], bReg[2];

#pragma unroll
    for (int i = 0; i < 4; i++) {
        const int f   = tid + i * 256;
        const int row = f >> 3;
        const int c4  = (f & 7) * 4;
        aReg[i] = *(const float4*)(A + (size_t)(bm + row) * K + c4);
    }
#pragma unroll
    for (int i = 0; i < 2; i++) {
        const int f   = tid + i * 256;
        const int row = f >> 3;
        const int c4  = (f & 7) * 4;
        bReg[i] = *(const float4*)(B + (size_t)(bn + row) * K + c4);
    }

    for (int k0 = 0; k0 < K; k0 += 32) {
        __syncthreads();
#pragma unroll
        for (int i = 0; i < 4; i++) {
            const int f   = tid + i * 256;
            const int row = f >> 3;
            const int c4  = (f & 7) * 4;
            As[row][c4 + 0] = f2tf32f(aReg[i].x);
            As[row][c4 + 1] = f2tf32f(aReg[i].y);
            As[row][c4 + 2] = f2tf32f(aReg[i].z);
            As[row][c4 + 3] = f2tf32f(aReg[i].w);
        }
#pragma unroll
        for (int i = 0; i < 2; i++) {
            const int f   = tid + i * 256;
            const int row = f >> 3;
            const int c4  = (f & 7) * 4;
            Bs[row][c4 + 0] = f2tf32f(bReg[i].x);
            Bs[row][c4 + 1] = f2tf32f(bReg[i].y);
            Bs[row][c4 + 2] = f2tf32f(bReg[i].z);
            Bs[row][c4 + 3] = f2tf32f(bReg[i].w);
        }
        __syncthreads();

        if (k0 + 32 < K) {
#pragma unroll
            for (int i = 0; i < 4; i++) {
                const int f   = tid + i * 256;
                const int row = f >> 3;
                const int c4  = (f & 7) * 4;
                aReg[i] = *(const float4*)(A + (size_t)(bm + row) * K + k0 + 32 + c4);
            }
#pragma unroll
            for (int i = 0; i < 2; i++) {
                const int f   = tid + i * 256;
                const int row = f >> 3;
                const int c4  = (f & 7) * 4;
                bReg[i] = *(const float4*)(B + (size_t)(bn + row) * K + k0 + 32 + c4);
            }
        }

#pragma unroll
        for (int ks = 0; ks < 4; ks++) {
            uint32_t af[2][4], bf[4][2];
#pragma unroll
            for (int mt = 0; mt < 2; mt++) {
                const int r = wm * 32 + mt * 16 + g;
                af[mt][0] = __float_as_uint(As[r    ][ks * 8 + t    ]);
                af[mt][1] = __float_as_uint(As[r + 8][ks * 8 + t    ]);
                af[mt][2] = __float_as_uint(As[r    ][ks * 8 + t + 4]);
                af[mt][3] = __float_as_uint(As[r + 8][ks * 8 + t + 4]);
            }
#pragma unroll
            for (int nt = 0; nt < 4; nt++) {
                const int c = wn * 32 + nt * 8 + g;
                bf[nt][0] = __float_as_uint(Bs[c][ks * 8 + t    ]);
                bf[nt][1] = __float_as_uint(Bs[c][ks * 8 + t + 4]);
            }
#pragma unroll
            for (int mt = 0; mt < 2; mt++)
#pragma unroll
                for (int nt = 0; nt < 4; nt++)
                    mma_tf32(acc[mt][nt], af[mt], bf[nt]);
        }
    }

#pragma unroll
    for (int mt = 0; mt < 2; mt++) {
#pragma unroll
        for (int nt = 0; nt < 4; nt++) {
            const int row = bm + wm * 32 + mt * 16 + g;
            const int col = bn + wn * 32 + nt * 8 + 2 * t;
            const float2 bv = *(const float2*)(bias + col);
            float2 o0, o1;
            o0.x = acc[mt][nt][0] + bv.x;
            o0.y = acc[mt][nt][1] + bv.y;
            o1.x = acc[mt][nt][2] + bv.x;
            o1.y = acc[mt][nt][3] + bv.y;
            *(float2*)(C + (size_t)row * N + col)       = o0;
            *(float2*)(C + (size_t)(row + 8) * N + col) = o1;
        }
    }
}

// ---------------------------------------------------------------------------
// Flash attention v4: R3 layouts + no-max softmax + fused normalize.
//   per kt tile: S = Q@K^T (mma) -> E = exp(S) -> write E to attn, accumulate
//   per-thread Z partials, shuffle E to A-fragments (RNA), ctx += E@V.
//   Epilogue: reduce Z, write ctx*invZ, rescale own attn strip by invZ
//   (strip is warm in L2; replaces the separate normalize kernel).
// ---------------------------------------------------------------------------
constexpr int AT_Q = 64;     // q rows per block (4 warps x 16 rows)
constexpr int K_LD = 68;     // frag banks (4g+t) conflict-free
constexpr int V_LD = 72;     // frag banks (8t+g) conflict-free

__global__ __launch_bounds__(128, 4) void attention_flash4_kernel(float* __restrict__ attn)
{
    __shared__ float Ks[64 * K_LD];
    __shared__ float Vs[64 * V_LD];
    __shared__ float invZs[AT_Q];

    const int tid  = threadIdx.x;
    const int lane = tid & 31;
    const int warp = tid >> 5;           // 0..3
    const int g    = lane >> 2;          // 0..7
    const int t    = lane & 3;           // 0..3

    const int qt = blockIdx.x;           // 0..31
    const int h  = blockIdx.y;
    const int b  = blockIdx.z;

    const float* Qg = g_q + (size_t)b * Sc * Dc + h * HDc;
    const float* Kg = g_k + (size_t)b * Sc * Dc + h * HDc;
    const float* Vg = g_v + (size_t)b * Sc * Dc + h * HDc;

    const int qrow = qt * AT_Q + warp * 16 + g;

    // ---- Q fragments in registers, scaled by 1/8, RNA tf32 (once) ----
    uint32_t qf[8][4];
#pragma unroll
    for (int ks = 0; ks < 8; ks++) {
        const float* q0 = Qg + (size_t)qrow * Dc + ks * 8;
        const float* q1 = Qg + (size_t)(qrow + 8) * Dc + ks * 8;
        qf[ks][0] = f2tf32(q0[t    ] * 0.125f);
        qf[ks][1] = f2tf32(q1[t    ] * 0.125f);
        qf[ks][2] = f2tf32(q0[t + 4] * 0.125f);
        qf[ks][3] = f2tf32(q1[t + 4] * 0.125f);
    }

    float ctx[8][4];
#pragma unroll
    for (int nt = 0; nt < 8; nt++)
#pragma unroll
        for (int i = 0; i < 4; i++) ctx[nt][i] = 0.f;

    float Z0 = 0.f, Z1 = 0.f;   // per-thread partials

    float* awr0 = attn + ((size_t)(b * Hc + h) * Sc + qrow) * Sc;
    float* awr1 = awr0 + (size_t)8 * Sc;

    for (int kt = 0; kt < Sc / 64; kt++) {
        // ---- load K and V tiles (coalesced float4), RNA tf32 ----
#pragma unroll
        for (int i = 0; i < 8; i++) {
            const int f  = tid + i * 128;
            const int r  = f >> 4;
            const int c4 = (f & 15) * 4;
            float4 kv = *(const float4*)(Kg + (size_t)(kt * 64 + r) * Dc + c4);
            Ks[r * K_LD + c4 + 0] = f2tf32f(kv.x);
            Ks[r * K_LD + c4 + 1] = f2tf32f(kv.y);
            Ks[r * K_LD + c4 + 2] = f2tf32f(kv.z);
            Ks[r * K_LD + c4 + 3] = f2tf32f(kv.w);
            float4 vv = *(const float4*)(Vg + (size_t)(kt * 64 + r) * Dc + c4);
            Vs[r * V_LD + c4 + 0] = f2tf32f(vv.x);
            Vs[r * V_LD + c4 + 1] = f2tf32f(vv.y);
            Vs[r * V_LD + c4 + 2] = f2tf32f(vv.z);
            Vs[r * V_LD + c4 + 3] = f2tf32f(vv.w);
        }
        __syncthreads();

        // ---- S = Q @ K^T ----
        float sacc[8][4];
#pragma unroll
        for (int nt = 0; nt < 8; nt++)
#pragma unroll
            for (int i = 0; i < 4; i++) sacc[nt][i] = 0.f;

#pragma unroll
        for (int ks = 0; ks < 8; ks++) {
#pragma unroll
            for (int nt = 0; nt < 8; nt++) {
                uint32_t bf[2];
                bf[0] = __float_as_uint(Ks[(nt * 8 + g) * K_LD + ks * 8 + t    ]);
                bf[1] = __float_as_uint(Ks[(nt * 8 + g) * K_LD + ks * 8 + t + 4]);
                mma_tf32(sacc[nt], qf[ks], bf);
            }
        }

        // ---- E = exp(S); Z partials; write E straight from regs ----
#pragma unroll
        for (int nt = 0; nt < 8; nt++) {
            sacc[nt][0] = __expf(sacc[nt][0]);
            sacc[nt][1] = __expf(sacc[nt][1]);
            sacc[nt][2] = __expf(sacc[nt][2]);
            sacc[nt][3] = __expf(sacc[nt][3]);
            Z0 += sacc[nt][0] + sacc[nt][1];
            Z1 += sacc[nt][2] + sacc[nt][3];
            const int col = kt * 64 + nt * 8 + 2 * t;
            *(float2*)(awr0 + col) = make_float2(sacc[nt][0], sacc[nt][1]);
            *(float2*)(awr1 + col) = make_float2(sacc[nt][2], sacc[nt][3]);
        }

        // ---- ctx += E @ V (accumulator -> A fragment via shuffles, RNA) ----
        const int srcA = (lane & ~3) | (t >> 1);
        const bool odd = (t & 1);
#pragma unroll
        for (int j = 0; j < 8; j++) {
            const float e0 = __shfl_sync(0xffffffff, sacc[j][0], srcA);
            const float o0 = __shfl_sync(0xffffffff, sacc[j][1], srcA);
            const float e2 = __shfl_sync(0xffffffff, sacc[j][0], srcA + 2);
            const float o2 = __shfl_sync(0xffffffff, sacc[j][1], srcA + 2);
            const float e1 = __shfl_sync(0xffffffff, sacc[j][2], srcA);
            const float o1 = __shfl_sync(0xffffffff, sacc[j][3], srcA);
            const float e3 = __shfl_sync(0xffffffff, sacc[j][2], srcA + 2);
            const float o3 = __shfl_sync(0xffffffff, sacc[j][3], srcA + 2);
            uint32_t af[4];
            af[0] = f2tf32(odd ? o0 : e0);
            af[1] = f2tf32(odd ? o1 : e1);
            af[2] = f2tf32(odd ? o2 : e2);
            af[3] = f2tf32(odd ? o3 : e3);
#pragma unroll
            for (int nt = 0; nt < 8; nt++) {
                uint32_t bf[2];
                bf[0] = __float_as_uint(Vs[(j * 8 + t    ) * V_LD + nt * 8 + g]);
                bf[1] = __float_as_uint(Vs[(j * 8 + t + 4) * V_LD + nt * 8 + g]);
                mma_tf32(ctx[nt], af, bf);
            }
        }
        __syncthreads();   // before next tile overwrites Ks/Vs
    }

    // ---- reduce Z across t-lanes (once) ----
    Z0 += __shfl_xor_sync(0xffffffff, Z0, 1);
    Z0 += __shfl_xor_sync(0xffffffff, Z0, 2);
    Z1 += __shfl_xor_sync(0xffffffff, Z1, 1);
    Z1 += __shfl_xor_sync(0xffffffff, Z1, 2);
    const float invZ0 = 1.0f / Z0;
    const float invZ1 = 1.0f / Z1;

    // ---- write normalized ctx ----
    float* c0 = g_ctx + (size_t)(b * Sc + qrow) * Dc + h * HDc;
    float* c1 = c0 + (size_t)8 * Dc;
#pragma unroll
    for (int nt = 0; nt < 8; nt++) {
        const int col = nt * 8 + 2 * t;
        *(float2*)(c0 + col) = make_float2(ctx[nt][0] * invZ0, ctx[nt][1] * invZ0);
        *(float2*)(c1 + col) = make_float2(ctx[nt][2] * invZ1, ctx[nt][3] * invZ1);
    }

    // ---- fused normalize: rescale own strip (warm in L2) ----
    if (t == 0) {
        invZs[warp * 16 + g]     = invZ0;
        invZs[warp * 16 + g + 8] = invZ1;
    }
    __syncthreads();   // invZs + all strip writes visible block-wide

    float* strip = attn + ((size_t)(b * Hc + h) * Sc + (size_t)qt * AT_Q) * Sc;
    for (int r = 0; r < AT_Q; r++) {
        const float iz = invZs[r];
        float* rp = strip + (size_t)r * Sc;
#pragma unroll
        for (int i = 0; i < 4; i++) {
            const int c = (tid + i * 128) * 4;
            float4 v = *(const float4*)(rp + c);
            v.x *= iz;  v.y *= iz;  v.z *= iz;  v.w *= iz;
            *(float4*)(rp + c) = v;
        }
    }
}

// ---------------------------------------------------------------------------
// kernel_launch
//   d_in: x, Wq, bq, Wk, bk, Wv, bv, Wo, bo   (all fp32)
//   d_out: [ out (B*S*D) | attention_weights (B*H*S*S) ]  fp32
// ---------------------------------------------------------------------------
extern "C" void kernel_launch(void* const* d_in, const int* in_sizes, int n_in,
                              void* d_out, int out_size)
{
    (void)in_sizes; (void)n_in; (void)out_size;
    const float* x  = (const float*)d_in[0];
    const float* Wq = (const float*)d_in[1];
    const float* bq = (const float*)d_in[2];
    const float* Wk = (const float*)d_in[3];
    const float* bk = (const float*)d_in[4];
    const float* Wv = (const float*)d_in[5];
    const float* bv = (const float*)d_in[6];
    const float* Wo = (const float*)d_in[7];
    const float* bo = (const float*)d_in[8];

    float* out  = (float*)d_out;
    float* attn = out + (size_t)Bc * Sc * Dc;

    float* gq;  cudaGetSymbolAddress((void**)&gq,  g_q);
    float* gk;  cudaGetSymbolAddress((void**)&gk,  g_k);
    float* gv;  cudaGetSymbolAddress((void**)&gv,  g_v);
    float* gc;  cudaGetSymbolAddress((void**)&gc,  g_ctx);

    dim3 gemmBlock(256);

    // Q/K/V projections fused into one launch
    dim3 qkvGrid(Dc / 64, Mc / 128, 3);      // (16, 32, 3)
    gemm3_tf32_nt_bias<<<qkvGrid, gemmBlock>>>(
        x, Wq, bq, gq, Wk, bk, gk, Wv, bv, gv, Mc, Dc, Dc);

    // Flash attention: weights (normalized in epilogue) + ctx
    dim3 attnGrid(Sc / AT_Q, Hc, Bc);        // (32, 16, 2)
    attention_flash4_kernel<<<attnGrid, 128>>>(attn);

    // Output projection
    dim3 oGrid(Dc / 64, Mc / 128, 1);        // (16, 32, 1)
    gemm3_tf32_nt_bias<<<oGrid, gemmBlock>>>(
        gc, Wo, bo, out, Wo, bo, out, Wo, bo, out, Mc, Dc, Dc);
}

// round 9
// speedup vs baseline: 1.1236x; 1.0179x over previous
#include <cuda_runtime.h>
#include <math.h>
#include <stdint.h>

// Problem constants
constexpr int Bc  = 2;
constexpr int Sc  = 2048;
constexpr int Dc  = 1024;
constexpr int Hc  = 16;
constexpr int HDc = 64;
constexpr int Mc  = Bc * Sc;          // 4096 rows for projections

// ---------------------------------------------------------------------------
// Device scratch (allocations forbidden; use __device__ globals)
// ---------------------------------------------------------------------------
__device__ float g_q[(size_t)Bc * Sc * Dc];
__device__ float g_k[(size_t)Bc * Sc * Dc];
__device__ float g_v[(size_t)Bc * Sc * Dc];
__device__ float g_ctx[(size_t)Bc * Sc * Dc];
__device__ float g_xr[(size_t)Mc * Dc];         // rounded x
__device__ float g_wr[4][(size_t)Dc * Dc];      // rounded Wq, Wk, Wv, Wo

// ---------------------------------------------------------------------------
// Helpers
// ---------------------------------------------------------------------------
__device__ __forceinline__ uint32_t f2tf32(float f) {
    uint32_t u;
    asm("cvt.rna.tf32.f32 %0, %1;" : "=r"(u) : "f"(f));
    return u;
}
__device__ __forceinline__ float f2tf32f(float f) {
    return __uint_as_float(f2tf32(f));
}

// D += A(16x8, tf32) * B(8x8, tf32)   (m16n8k8, row.col)
__device__ __forceinline__ void mma_tf32(float* d, const uint32_t* a, const uint32_t* b) {
    asm volatile(
        "mma.sync.aligned.m16n8k8.row.col.f32.tf32.tf32.f32 "
        "{%0,%1,%2,%3}, {%4,%5,%6,%7}, {%8,%9}, {%0,%1,%2,%3};"
        : "+f"(d[0]), "+f"(d[1]), "+f"(d[2]), "+f"(d[3])
        : "r"(a[0]), "r"(a[1]), "r"(a[2]), "r"(a[3]), "r"(b[0]), "r"(b[1]));
}

// ---------------------------------------------------------------------------
// One-shot RNA rounding of x and all four weight matrices.
// ---------------------------------------------------------------------------
__global__ __launch_bounds__(256) void round_inputs(
    const float* __restrict__ x,
    const float* __restrict__ Wq, const float* __restrict__ Wk,
    const float* __restrict__ Wv, const float* __restrict__ Wo)
{
    const size_t NX = (size_t)Mc * Dc / 4;      // float4 count for x
    const size_t NW = (size_t)Dc * Dc / 4;      // float4 count per W
    const size_t total = NX + 4 * NW;
    const size_t stride = (size_t)gridDim.x * blockDim.x;

    for (size_t i = (size_t)blockIdx.x * blockDim.x + threadIdx.x; i < total; i += stride) {
        const float4* src;
        float4* dst;
        if (i < NX) {
            src = (const float4*)x + i;
            dst = (float4*)g_xr + i;
        } else {
            const size_t j = i - NX;
            const int w = (int)(j / NW);
            const size_t o = j % NW;
            const float* ws = (w == 0) ? Wq : (w == 1) ? Wk : (w == 2) ? Wv : Wo;
            src = (const float4*)ws + o;
            dst = (float4*)g_wr[w] + o;
        }
        const float4 v = *src;
        *dst = make_float4(f2tf32f(v.x), f2tf32f(v.y), f2tf32f(v.z), f2tf32f(v.w));
    }
}

// ---------------------------------------------------------------------------
// tf32 GEMM (NT), 3 problems fused via blockIdx.z. Inputs pre-rounded, so the
// fill path is a pure copy. roundOut=1 rounds outputs (for q/k/v scratch).
//   Cz[m,n] = sum_k A[m,k] * Wz[n,k] + bz[n]
// BM=128, BN=64, BK=32, 256 threads = 8 warps (4m x 2n), warp tile 32x32.
// ---------------------------------------------------------------------------
__global__ __launch_bounds__(256) void gemm3_tf32_nt_bias(
    const float* __restrict__ A,
    const float* __restrict__ W0, const float* __restrict__ b0, float* __restrict__ C0,
    const float* __restrict__ W1, const float* __restrict__ b1, float* __restrict__ C1,
    const float* __restrict__ W2, const float* __restrict__ b2, float* __restrict__ C2,
    int M, int N, int K, int roundOut)
{
    const int z = blockIdx.z;
    const float* B    = (z == 0) ? W0 : (z == 1) ? W1 : W2;
    const float* bias = (z == 0) ? b0 : (z == 1) ? b1 : b2;
    float*       C    = (z == 0) ? C0 : (z == 1) ? C1 : C2;

    __shared__ float As[128][36];
    __shared__ float Bs[64][36];

    const int tid  = threadIdx.x;
    const int lane = tid & 31;
    const int warp = tid >> 5;
    const int wm   = warp >> 1;          // 0..3
    const int wn   = warp & 1;           // 0..1
    const int g    = lane >> 2;          // 0..7
    const int t    = lane & 3;           // 0..3
    const int bm   = blockIdx.y * 128;
    const int bn   = blockIdx.x * 64;

    float acc[2][4][4];
#pragma unroll
    for (int mt = 0; mt < 2; mt++)
#pragma unroll
        for (int nt = 0; nt < 4; nt++)
#pragma unroll
            for (int i = 0; i < 4; i++) acc[mt][nt][i] = 0.f;

    float4 aReg[4], bReg[2];

#pragma unroll
    for (int i = 0; i < 4; i++) {
        const int f   = tid + i * 256;
        const int row = f >> 3;
        const int c4  = (f & 7) * 4;
        aReg[i] = *(const float4*)(A + (size_t)(bm + row) * K + c4);
    }
#pragma unroll
    for (int i = 0; i < 2; i++) {
        const int f   = tid + i * 256;
        const int row = f >> 3;
        const int c4  = (f & 7) * 4;
        bReg[i] = *(const float4*)(B + (size_t)(bn + row) * K + c4);
    }

    for (int k0 = 0; k0 < K; k0 += 32) {
        __syncthreads();
#pragma unroll
        for (int i = 0; i < 4; i++) {
            const int f   = tid + i * 256;
            const int row = f >> 3;
            const int c4  = (f & 7) * 4;
            As[row][c4 + 0] = aReg[i].x;
            As[row][c4 + 1] = aReg[i].y;
            As[row][c4 + 2] = aReg[i].z;
            As[row][c4 + 3] = aReg[i].w;
        }
#pragma unroll
        for (int i = 0; i < 2; i++) {
            const int f   = tid + i * 256;
            const int row = f >> 3;
            const int c4  = (f & 7) * 4;
            Bs[row][c4 + 0] = bReg[i].x;
            Bs[row][c4 + 1] = bReg[i].y;
            Bs[row][c4 + 2] = bReg[i].z;
            Bs[row][c4 + 3] = bReg[i].w;
        }
        __syncthreads();

        if (k0 + 32 < K) {
#pragma unroll
            for (int i = 0; i < 4; i++) {
                const int f   = tid + i * 256;
                const int row = f >> 3;
                const int c4  = (f & 7) * 4;
                aReg[i] = *(const float4*)(A + (size_t)(bm + row) * K + k0 + 32 + c4);
            }
#pragma unroll
            for (int i = 0; i < 2; i++) {
                const int f   = tid + i * 256;
                const int row = f >> 3;
                const int c4  = (f & 7) * 4;
                bReg[i] = *(const float4*)(B + (size_t)(bn + row) * K + k0 + 32 + c4);
            }
        }

#pragma unroll
        for (int ks = 0; ks < 4; ks++) {
            uint32_t af[2][4], bf[4][2];
#pragma unroll
            for (int mt = 0; mt < 2; mt++) {
                const int r = wm * 32 + mt * 16 + g;
                af[mt][0] = __float_as_uint(As[r    ][ks * 8 + t    ]);
                af[mt][1] = __float_as_uint(As[r + 8][ks * 8 + t    ]);
                af[mt][2] = __float_as_uint(As[r    ][ks * 8 + t + 4]);
                af[mt][3] = __float_as_uint(As[r + 8][ks * 8 + t + 4]);
            }
#pragma unroll
            for (int nt = 0; nt < 4; nt++) {
                const int c = wn * 32 + nt * 8 + g;
                bf[nt][0] = __float_as_uint(Bs[c][ks * 8 + t    ]);
                bf[nt][1] = __float_as_uint(Bs[c][ks * 8 + t + 4]);
            }
#pragma unroll
            for (int mt = 0; mt < 2; mt++)
#pragma unroll
                for (int nt = 0; nt < 4; nt++)
                    mma_tf32(acc[mt][nt], af[mt], bf[nt]);
        }
    }

#pragma unroll
    for (int mt = 0; mt < 2; mt++) {
#pragma unroll
        for (int nt = 0; nt < 4; nt++) {
            const int row = bm + wm * 32 + mt * 16 + g;
            const int col = bn + wn * 32 + nt * 8 + 2 * t;
            const float2 bv = *(const float2*)(bias + col);
            float2 o0, o1;
            o0.x = acc[mt][nt][0] + bv.x;
            o0.y = acc[mt][nt][1] + bv.y;
            o1.x = acc[mt][nt][2] + bv.x;
            o1.y = acc[mt][nt][3] + bv.y;
            if (roundOut) {
                o0.x = f2tf32f(o0.x);  o0.y = f2tf32f(o0.y);
                o1.x = f2tf32f(o1.x);  o1.y = f2tf32f(o1.y);
            }
            *(float2*)(C + (size_t)row * N + col)       = o0;
            *(float2*)(C + (size_t)(row + 8) * N + col) = o1;
        }
    }
}

// ---------------------------------------------------------------------------
// Flash attention v4b: q/k/v arrive pre-rounded, fills are pure copies.
//   per kt tile: S = Q@K^T (mma) -> E = exp(S) -> write E to attn, accumulate
//   per-thread Z partials, shuffle E to A-fragments (RNA), ctx += E@V.
//   Epilogue: reduce Z, write rounded ctx*invZ, rescale own attn strip.
// ---------------------------------------------------------------------------
constexpr int AT_Q = 64;     // q rows per block (4 warps x 16 rows)
constexpr int K_LD = 68;     // frag banks (4g+t) conflict-free
constexpr int V_LD = 72;     // frag banks (8t+g) conflict-free

__global__ __launch_bounds__(128, 4) void attention_flash4_kernel(float* __restrict__ attn)
{
    __shared__ float Ks[64 * K_LD];
    __shared__ float Vs[64 * V_LD];
    __shared__ float invZs[AT_Q];

    const int tid  = threadIdx.x;
    const int lane = tid & 31;
    const int warp = tid >> 5;           // 0..3
    const int g    = lane >> 2;          // 0..7
    const int t    = lane & 3;           // 0..3

    const int qt = blockIdx.x;           // 0..31
    const int h  = blockIdx.y;
    const int b  = blockIdx.z;

    const float* Qg = g_q + (size_t)b * Sc * Dc + h * HDc;
    const float* Kg = g_k + (size_t)b * Sc * Dc + h * HDc;
    const float* Vg = g_v + (size_t)b * Sc * Dc + h * HDc;

    const int qrow = qt * AT_Q + warp * 16 + g;

    // ---- Q fragments: pre-rounded; x0.125 (2^-3) keeps tf32 exactness ----
    uint32_t qf[8][4];
#pragma unroll
    for (int ks = 0; ks < 8; ks++) {
        const float* q0 = Qg + (size_t)qrow * Dc + ks * 8;
        const float* q1 = Qg + (size_t)(qrow + 8) * Dc + ks * 8;
        qf[ks][0] = __float_as_uint(q0[t    ] * 0.125f);
        qf[ks][1] = __float_as_uint(q1[t    ] * 0.125f);
        qf[ks][2] = __float_as_uint(q0[t + 4] * 0.125f);
        qf[ks][3] = __float_as_uint(q1[t + 4] * 0.125f);
    }

    float ctx[8][4];
#pragma unroll
    for (int nt = 0; nt < 8; nt++)
#pragma unroll
        for (int i = 0; i < 4; i++) ctx[nt][i] = 0.f;

    float Z0 = 0.f, Z1 = 0.f;

    float* awr0 = attn + ((size_t)(b * Hc + h) * Sc + qrow) * Sc;
    float* awr1 = awr0 + (size_t)8 * Sc;

    for (int kt = 0; kt < Sc / 64; kt++) {
        // ---- K/V tile fill: pure float4 copies ----
#pragma unroll
        for (int i = 0; i < 8; i++) {
            const int f  = tid + i * 128;
            const int r  = f >> 4;
            const int c4 = (f & 15) * 4;
            *(float4*)(Ks + r * K_LD + c4) =
                *(const float4*)(Kg + (size_t)(kt * 64 + r) * Dc + c4);
            *(float4*)(Vs + r * V_LD + c4) =
                *(const float4*)(Vg + (size_t)(kt * 64 + r) * Dc + c4);
        }
        __syncthreads();

        // ---- S = Q @ K^T ----
        float sacc[8][4];
#pragma unroll
        for (int nt = 0; nt < 8; nt++)
#pragma unroll
            for (int i = 0; i < 4; i++) sacc[nt][i] = 0.f;

#pragma unroll
        for (int ks = 0; ks < 8; ks++) {
#pragma unroll
            for (int nt = 0; nt < 8; nt++) {
                uint32_t bf[2];
                bf[0] = __float_as_uint(Ks[(nt * 8 + g) * K_LD + ks * 8 + t    ]);
                bf[1] = __float_as_uint(Ks[(nt * 8 + g) * K_LD + ks * 8 + t + 4]);
                mma_tf32(sacc[nt], qf[ks], bf);
            }
        }

        // ---- E = exp(S); Z partials; write E straight from regs ----
#pragma unroll
        for (int nt = 0; nt < 8; nt++) {
            sacc[nt][0] = __expf(sacc[nt][0]);
            sacc[nt][1] = __expf(sacc[nt][1]);
            sacc[nt][2] = __expf(sacc[nt][2]);
            sacc[nt][3] = __expf(sacc[nt][3]);
            Z0 += sacc[nt][0] + sacc[nt][1];
            Z1 += sacc[nt][2] + sacc[nt][3];
            const int col = kt * 64 + nt * 8 + 2 * t;
            *(float2*)(awr0 + col) = make_float2(sacc[nt][0], sacc[nt][1]);
            *(float2*)(awr1 + col) = make_float2(sacc[nt][2], sacc[nt][3]);
        }

        // ---- ctx += E @ V (accumulator -> A fragment via shuffles, RNA) ----
        const int srcA = (lane & ~3) | (t >> 1);
        const bool odd = (t & 1);
#pragma unroll
        for (int j = 0; j < 8; j++) {
            const float e0 = __shfl_sync(0xffffffff, sacc[j][0], srcA);
            const float o0 = __shfl_sync(0xffffffff, sacc[j][1], srcA);
            const float e2 = __shfl_sync(0xffffffff, sacc[j][0], srcA + 2);
            const float o2 = __shfl_sync(0xffffffff, sacc[j][1], srcA + 2);
            const float e1 = __shfl_sync(0xffffffff, sacc[j][2], srcA);
            const float o1 = __shfl_sync(0xffffffff, sacc[j][3], srcA);
            const float e3 = __shfl_sync(0xffffffff, sacc[j][2], srcA + 2);
            const float o3 = __shfl_sync(0xffffffff, sacc[j][3], srcA + 2);
            uint32_t af[4];
            af[0] = f2tf32(odd ? o0 : e0);
            af[1] = f2tf32(odd ? o1 : e1);
            af[2] = f2tf32(odd ? o2 : e2);
            af[3] = f2tf32(odd ? o3 : e3);
#pragma unroll
            for (int nt = 0; nt < 8; nt++) {
                uint32_t bf[2];
                bf[0] = __float_as_uint(Vs[(j * 8 + t    ) * V_LD + nt * 8 + g]);
                bf[1] = __float_as_uint(Vs[(j * 8 + t + 4) * V_LD + nt * 8 + g]);
                mma_tf32(ctx[nt], af, bf);
            }
        }
        __syncthreads();   // before next tile overwrites Ks/Vs
    }

    // ---- reduce Z across t-lanes (once) ----
    Z0 += __shfl_xor_sync(0xffffffff, Z0, 1);
    Z0 += __shfl_xor_sync(0xffffffff, Z0, 2);
    Z1 += __shfl_xor_sync(0xffffffff, Z1, 1);
    Z1 += __shfl_xor_sync(0xffffffff, Z1, 2);
    const float invZ0 = 1.0f / Z0;
    const float invZ1 = 1.0f / Z1;

    // ---- write rounded normalized ctx (same rounding point as before) ----
    float* c0 = g_ctx + (size_t)(b * Sc + qrow) * Dc + h * HDc;
    float* c1 = c0 + (size_t)8 * Dc;
#pragma unroll
    for (int nt = 0; nt < 8; nt++) {
        const int col = nt * 8 + 2 * t;
        *(float2*)(c0 + col) = make_float2(f2tf32f(ctx[nt][0] * invZ0),
                                           f2tf32f(ctx[nt][1] * invZ0));
        *(float2*)(c1 + col) = make_float2(f2tf32f(ctx[nt][2] * invZ1),
                                           f2tf32f(ctx[nt][3] * invZ1));
    }

    // ---- fused normalize: rescale own strip (warm in L2) ----
    if (t == 0) {
        invZs[warp * 16 + g]     = invZ0;
        invZs[warp * 16 + g + 8] = invZ1;
    }
    __syncthreads();

    float* strip = attn + ((size_t)(b * Hc + h) * Sc + (size_t)qt * AT_Q) * Sc;
    for (int r = 0; r < AT_Q; r++) {
        const float iz = invZs[r];
        float* rp = strip + (size_t)r * Sc;
#pragma unroll
        for (int i = 0; i < 4; i++) {
            const int c = (tid + i * 128) * 4;
            float4 v = *(const float4*)(rp + c);
            v.x *= iz;  v.y *= iz;  v.z *= iz;  v.w *= iz;
            *(float4*)(rp + c) = v;
        }
    }
}

// ---------------------------------------------------------------------------
// kernel_launch
//   d_in: x, Wq, bq, Wk, bk, Wv, bv, Wo, bo   (all fp32)
//   d_out: [ out (B*S*D) | attention_weights (B*H*S*S) ]  fp32
// ---------------------------------------------------------------------------
extern "C" void kernel_launch(void* const* d_in, const int* in_sizes, int n_in,
                              void* d_out, int out_size)
{
    (void)in_sizes; (void)n_in; (void)out_size;
    const float* x  = (const float*)d_in[0];
    const float* Wq = (const float*)d_in[1];
    const float* bq = (const float*)d_in[2];
    const float* Wk = (const float*)d_in[3];
    const float* bk = (const float*)d_in[4];
    const float* Wv = (const float*)d_in[5];
    const float* bv = (const float*)d_in[6];
    const float* Wo = (const float*)d_in[7];
    const float* bo = (const float*)d_in[8];

    float* out  = (float*)d_out;
    float* attn = out + (size_t)Bc * Sc * Dc;

    float* gq;  cudaGetSymbolAddress((void**)&gq,  g_q);
    float* gk;  cudaGetSymbolAddress((void**)&gk,  g_k);
    float* gv;  cudaGetSymbolAddress((void**)&gv,  g_v);
    float* gc;  cudaGetSymbolAddress((void**)&gc,  g_ctx);
    float* gxr; cudaGetSymbolAddress((void**)&gxr, g_xr);
    float* gwr; cudaGetSymbolAddress((void**)&gwr, g_wr);

    const float* wq = gwr;
    const float* wk = gwr + (size_t)Dc * Dc;
    const float* wv = gwr + 2 * (size_t)Dc * Dc;
    const float* wo = gwr + 3 * (size_t)Dc * Dc;

    // One-shot RNA rounding of x and all weights
    round_inputs<<<1024, 256>>>(x, Wq, Wk, Wv, Wo);

    dim3 gemmBlock(256);

    // Q/K/V projections (rounded outputs for the attention stage)
    dim3 qkvGrid(Dc / 64, Mc / 128, 3);      // (16, 32, 3)
    gemm3_tf32_nt_bias<<<qkvGrid, gemmBlock>>>(
        gxr, wq, bq, gq, wk, bk, gk, wv, bv, gv, Mc, Dc, Dc, 1);

    // Flash attention: weights (normalized in epilogue) + rounded ctx
    dim3 attnGrid(Sc / AT_Q, Hc, Bc);        // (32, 16, 2)
    attention_flash4_kernel<<<attnGrid, 128>>>(attn);

    // Output projection (exact fp32 output)
    dim3 oGrid(Dc / 64, Mc / 128, 1);        // (16, 32, 1)
    gemm3_tf32_nt_bias<<<oGrid, gemmBlock>>>(
        gc, wo, bo, out, wo, bo, out, wo, bo, out, Mc, Dc, Dc, 0);
}

// round 11
// speedup vs baseline: 1.1717x; 1.0429x over previous
#include <cuda_runtime.h>
#include <math.h>
#include <stdint.h>

// Problem constants
constexpr int Bc  = 2;
constexpr int Sc  = 2048;
constexpr int Dc  = 1024;
constexpr int Hc  = 16;
constexpr int HDc = 64;
constexpr int Mc  = Bc * Sc;          // 4096 rows for projections

// ---------------------------------------------------------------------------
// Device scratch (allocations forbidden; use __device__ globals)
// ---------------------------------------------------------------------------
__device__ float g_q[(size_t)Bc * Sc * Dc];
__device__ float g_k[(size_t)Bc * Sc * Dc];
__device__ float g_v[(size_t)Bc * Sc * Dc];
__device__ float g_ctx[(size_t)Bc * Sc * Dc];
__device__ float g_xr[(size_t)Mc * Dc];         // rounded x
__device__ float g_wr[4][(size_t)Dc * Dc];      // rounded Wq, Wk, Wv, Wo

// ---------------------------------------------------------------------------
// Helpers
// ---------------------------------------------------------------------------
__device__ __forceinline__ uint32_t f2tf32(float f) {
    uint32_t u;
    asm("cvt.rna.tf32.f32 %0, %1;" : "=r"(u) : "f"(f));
    return u;
}
__device__ __forceinline__ float f2tf32f(float f) {
    return __uint_as_float(f2tf32(f));
}

// D += A(16x8, tf32) * B(8x8, tf32)   (m16n8k8, row.col)
__device__ __forceinline__ void mma_tf32(float* d, const uint32_t* a, const uint32_t* b) {
    asm volatile(
        "mma.sync.aligned.m16n8k8.row.col.f32.tf32.tf32.f32 "
        "{%0,%1,%2,%3}, {%4,%5,%6,%7}, {%8,%9}, {%0,%1,%2,%3};"
        : "+f"(d[0]), "+f"(d[1]), "+f"(d[2]), "+f"(d[3])
        : "r"(a[0]), "r"(a[1]), "r"(a[2]), "r"(a[3]), "r"(b[0]), "r"(b[1]));
}

__device__ __forceinline__ void cp16(uint32_t smem_dst, const void* gmem_src) {
    asm volatile("cp.async.cg.shared.global [%0], [%1], 16;"
                 :: "r"(smem_dst), "l"(gmem_src));
}
__device__ __forceinline__ void cp_commit() {
    asm volatile("cp.async.commit_group;");
}
template <int N>
__device__ __forceinline__ void cp_wait() {
    asm volatile("cp.async.wait_group %0;" :: "n"(N));
}

// ---------------------------------------------------------------------------
// One-shot RNA rounding of x and all four weight matrices.
// ---------------------------------------------------------------------------
__global__ __launch_bounds__(256) void round_inputs(
    const float* __restrict__ x,
    const float* __restrict__ Wq, const float* __restrict__ Wk,
    const float* __restrict__ Wv, const float* __restrict__ Wo)
{
    const size_t NX = (size_t)Mc * Dc / 4;
    const size_t NW = (size_t)Dc * Dc / 4;
    const size_t total = NX + 4 * NW;
    const size_t stride = (size_t)gridDim.x * blockDim.x;

    for (size_t i = (size_t)blockIdx.x * blockDim.x + threadIdx.x; i < total; i += stride) {
        const float4* src;
        float4* dst;
        if (i < NX) {
            src = (const float4*)x + i;
            dst = (float4*)g_xr + i;
        } else {
            const size_t j = i - NX;
            const int w = (int)(j / NW);
            const size_t o = j % NW;
            const float* ws = (w == 0) ? Wq : (w == 1) ? Wk : (w == 2) ? Wv : Wo;
            src = (const float4*)ws + o;
            dst = (float4*)g_wr[w] + o;
        }
        const float4 v = *src;
        *dst = make_float4(f2tf32f(v.x), f2tf32f(v.y), f2tf32f(v.z), f2tf32f(v.w));
    }
}

// ---------------------------------------------------------------------------
// tf32 GEMM v3 (NT), 3 problems via blockIdx.z, cp.async double-buffered.
//   Cz[m,n] = sum_k A[m,k] * Wz[n,k] + bz[n]    (M=Mc, N=K=Dc fixed)
// BM=128, BN=64, BK=32, 256 threads = 8 warps (4m x 2n), warp tile 32x32.
// Inputs pre-rounded; fills are cp.async 16B copies into [*][36] layout.
// ---------------------------------------------------------------------------
constexpr int NKC     = Dc / 32;                 // 32 k-chunks
constexpr int A_FLTS  = 128 * 36;                // one A buffer (floats)
constexpr int B_FLTS  = 64 * 36;
constexpr int G_SMEM  = 2 * (A_FLTS + B_FLTS) * 4;   // 55296 B

__global__ __launch_bounds__(256, 3) void gemm3_cp(
    const float* __restrict__ A,
    const float* __restrict__ W0, const float* __restrict__ b0, float* __restrict__ C0,
    const float* __restrict__ W1, const float* __restrict__ b1, float* __restrict__ C1,
    const float* __restrict__ W2, const float* __restrict__ b2, float* __restrict__ C2,
    int roundOut)
{
    const int z = blockIdx.z;
    const float* B    = (z == 0) ? W0 : (z == 1) ? W1 : W2;
    const float* bias = (z == 0) ? b0 : (z == 1) ? b1 : b2;
    float*       C    = (z == 0) ? C0 : (z == 1) ? C1 : C2;

    extern __shared__ float sm[];
    // layout: As buf0 | As buf1 | Bs buf0 | Bs buf1
    float* AsBase = sm;
    float* BsBase = sm + 2 * A_FLTS;

    const int tid  = threadIdx.x;
    const int lane = tid & 31;
    const int warp = tid >> 5;
    const int wm   = warp >> 1;          // 0..3
    const int wn   = warp & 1;           // 0..1
    const int g    = lane >> 2;          // 0..7
    const int t    = lane & 3;           // 0..3
    const int bm   = blockIdx.y * 128;
    const int bn   = blockIdx.x * 64;

    float acc[2][4][4];
#pragma unroll
    for (int mt = 0; mt < 2; mt++)
#pragma unroll
        for (int nt = 0; nt < 4; nt++)
#pragma unroll
            for (int i = 0; i < 4; i++) acc[mt][nt][i] = 0.f;

    // ---- async copy of one 32-k chunk into buffer `buf` ----
    auto copy_chunk = [&](int kc, int buf) {
        const int k0 = kc * 32;
        uint32_t asm_base = (uint32_t)__cvta_generic_to_shared(AsBase + buf * A_FLTS);
        uint32_t bsm_base = (uint32_t)__cvta_generic_to_shared(BsBase + buf * B_FLTS);
#pragma unroll
        for (int i = 0; i < 4; i++) {
            const int f   = tid + i * 256;
            const int row = f >> 3;
            const int c4  = (f & 7) * 4;
            cp16(asm_base + (row * 36 + c4) * 4,
                 A + (size_t)(bm + row) * Dc + k0 + c4);
        }
#pragma unroll
        for (int i = 0; i < 2; i++) {
            const int f   = tid + i * 256;
            const int row = f >> 3;
            const int c4  = (f & 7) * 4;
            cp16(bsm_base + (row * 36 + c4) * 4,
                 B + (size_t)(bn + row) * Dc + k0 + c4);
        }
        cp_commit();
    };

    copy_chunk(0, 0);

    for (int it = 0; it < NKC; it++) {
        const int cur = it & 1;
        if (it + 1 < NKC) {
            copy_chunk(it + 1, cur ^ 1);
            cp_wait<1>();
        } else {
            cp_wait<0>();
        }
        __syncthreads();

        const float* As = AsBase + cur * A_FLTS;
        const float* Bs = BsBase + cur * B_FLTS;
#pragma unroll
        for (int ks = 0; ks < 4; ks++) {
            uint32_t af[2][4], bf[4][2];
#pragma unroll
            for (int mt = 0; mt < 2; mt++) {
                const int r = wm * 32 + mt * 16 + g;
                af[mt][0] = __float_as_uint(As[(r    ) * 36 + ks * 8 + t    ]);
                af[mt][1] = __float_as_uint(As[(r + 8) * 36 + ks * 8 + t    ]);
                af[mt][2] = __float_as_uint(As[(r    ) * 36 + ks * 8 + t + 4]);
                af[mt][3] = __float_as_uint(As[(r + 8) * 36 + ks * 8 + t + 4]);
            }
#pragma unroll
            for (int nt = 0; nt < 4; nt++) {
                const int c = wn * 32 + nt * 8 + g;
                bf[nt][0] = __float_as_uint(Bs[c * 36 + ks * 8 + t    ]);
                bf[nt][1] = __float_as_uint(Bs[c * 36 + ks * 8 + t + 4]);
            }
#pragma unroll
            for (int mt = 0; mt < 2; mt++)
#pragma unroll
                for (int nt = 0; nt < 4; nt++)
                    mma_tf32(acc[mt][nt], af[mt], bf[nt]);
        }
        __syncthreads();   // compute done before next prefetch overwrites this buf
    }

    // epilogue
#pragma unroll
    for (int mt = 0; mt < 2; mt++) {
#pragma unroll
        for (int nt = 0; nt < 4; nt++) {
            const int row = bm + wm * 32 + mt * 16 + g;
            const int col = bn + wn * 32 + nt * 8 + 2 * t;
            const float2 bv = *(const float2*)(bias + col);
            float2 o0, o1;
            o0.x = acc[mt][nt][0] + bv.x;
            o0.y = acc[mt][nt][1] + bv.y;
            o1.x = acc[mt][nt][2] + bv.x;
            o1.y = acc[mt][nt][3] + bv.y;
            if (roundOut) {
                o0.x = f2tf32f(o0.x);  o0.y = f2tf32f(o0.y);
                o1.x = f2tf32f(o1.x);  o1.y = f2tf32f(o1.y);
            }
            *(float2*)(C + (size_t)row * Dc + col)       = o0;
            *(float2*)(C + (size_t)(row + 8) * Dc + col) = o1;
        }
    }
}

// ---------------------------------------------------------------------------
// Flash attention v4b (unchanged from R9): q/k/v pre-rounded, pure-copy fills.
// ---------------------------------------------------------------------------
constexpr int AT_Q = 64;     // q rows per block (4 warps x 16 rows)
constexpr int K_LD = 68;     // frag banks (4g+t) conflict-free
constexpr int V_LD = 72;     // frag banks (8t+g) conflict-free

__global__ __launch_bounds__(128, 4) void attention_flash4_kernel(float* __restrict__ attn)
{
    __shared__ float Ks[64 * K_LD];
    __shared__ float Vs[64 * V_LD];
    __shared__ float invZs[AT_Q];

    const int tid  = threadIdx.x;
    const int lane = tid & 31;
    const int warp = tid >> 5;           // 0..3
    const int g    = lane >> 2;          // 0..7
    const int t    = lane & 3;           // 0..3

    const int qt = blockIdx.x;           // 0..31
    const int h  = blockIdx.y;
    const int b  = blockIdx.z;

    const float* Qg = g_q + (size_t)b * Sc * Dc + h * HDc;
    const float* Kg = g_k + (size_t)b * Sc * Dc + h * HDc;
    const float* Vg = g_v + (size_t)b * Sc * Dc + h * HDc;

    const int qrow = qt * AT_Q + warp * 16 + g;

    uint32_t qf[8][4];
#pragma unroll
    for (int ks = 0; ks < 8; ks++) {
        const float* q0 = Qg + (size_t)qrow * Dc + ks * 8;
        const float* q1 = Qg + (size_t)(qrow + 8) * Dc + ks * 8;
        qf[ks][0] = __float_as_uint(q0[t    ] * 0.125f);
        qf[ks][1] = __float_as_uint(q1[t    ] * 0.125f);
        qf[ks][2] = __float_as_uint(q0[t + 4] * 0.125f);
        qf[ks][3] = __float_as_uint(q1[t + 4] * 0.125f);
    }

    float ctx[8][4];
#pragma unroll
    for (int nt = 0; nt < 8; nt++)
#pragma unroll
        for (int i = 0; i < 4; i++) ctx[nt][i] = 0.f;

    float Z0 = 0.f, Z1 = 0.f;

    float* awr0 = attn + ((size_t)(b * Hc + h) * Sc + qrow) * Sc;
    float* awr1 = awr0 + (size_t)8 * Sc;

    for (int kt = 0; kt < Sc / 64; kt++) {
#pragma unroll
        for (int i = 0; i < 8; i++) {
            const int f  = tid + i * 128;
            const int r  = f >> 4;
            const int c4 = (f & 15) * 4;
            *(float4*)(Ks + r * K_LD + c4) =
                *(const float4*)(Kg + (size_t)(kt * 64 + r) * Dc + c4);
            *(float4*)(Vs + r * V_LD + c4) =
                *(const float4*)(Vg + (size_t)(kt * 64 + r) * Dc + c4);
        }
        __syncthreads();

        float sacc[8][4];
#pragma unroll
        for (int nt = 0; nt < 8; nt++)
#pragma unroll
            for (int i = 0; i < 4; i++) sacc[nt][i] = 0.f;

#pragma unroll
        for (int ks = 0; ks < 8; ks++) {
#pragma unroll
            for (int nt = 0; nt < 8; nt++) {
                uint32_t bf[2];
                bf[0] = __float_as_uint(Ks[(nt * 8 + g) * K_LD + ks * 8 + t    ]);
                bf[1] = __float_as_uint(Ks[(nt * 8 + g) * K_LD + ks * 8 + t + 4]);
                mma_tf32(sacc[nt], qf[ks], bf);
            }
        }

#pragma unroll
        for (int nt = 0; nt < 8; nt++) {
            sacc[nt][0] = __expf(sacc[nt][0]);
            sacc[nt][1] = __expf(sacc[nt][1]);
            sacc[nt][2] = __expf(sacc[nt][2]);
            sacc[nt][3] = __expf(sacc[nt][3]);
            Z0 += sacc[nt][0] + sacc[nt][1];
            Z1 += sacc[nt][2] + sacc[nt][3];
            const int col = kt * 64 + nt * 8 + 2 * t;
            *(float2*)(awr0 + col) = make_float2(sacc[nt][0], sacc[nt][1]);
            *(float2*)(awr1 + col) = make_float2(sacc[nt][2], sacc[nt][3]);
        }

        const int srcA = (lane & ~3) | (t >> 1);
        const bool odd = (t & 1);
#pragma unroll
        for (int j = 0; j < 8; j++) {
            const float e0 = __shfl_sync(0xffffffff, sacc[j][0], srcA);
            const float o0 = __shfl_sync(0xffffffff, sacc[j][1], srcA);
            const float e2 = __shfl_sync(0xffffffff, sacc[j][0], srcA + 2);
            const float o2 = __shfl_sync(0xffffffff, sacc[j][1], srcA + 2);
            const float e1 = __shfl_sync(0xffffffff, sacc[j][2], srcA);
            const float o1 = __shfl_sync(0xffffffff, sacc[j][3], srcA);
            const float e3 = __shfl_sync(0xffffffff, sacc[j][2], srcA + 2);
            const float o3 = __shfl_sync(0xffffffff, sacc[j][3], srcA + 2);
            uint32_t af[4];
            af[0] = f2tf32(odd ? o0 : e0);
            af[1] = f2tf32(odd ? o1 : e1);
            af[2] = f2tf32(odd ? o2 : e2);
            af[3] = f2tf32(odd ? o3 : e3);
#pragma unroll
            for (int nt = 0; nt < 8; nt++) {
                uint32_t bf[2];
                bf[0] = __float_as_uint(Vs[(j * 8 + t    ) * V_LD + nt * 8 + g]);
                bf[1] = __float_as_uint(Vs[(j * 8 + t + 4) * V_LD + nt * 8 + g]);
                mma_tf32(ctx[nt], af, bf);
            }
        }
        __syncthreads();
    }

    Z0 += __shfl_xor_sync(0xffffffff, Z0, 1);
    Z0 += __shfl_xor_sync(0xffffffff, Z0, 2);
    Z1 += __shfl_xor_sync(0xffffffff, Z1, 1);
    Z1 += __shfl_xor_sync(0xffffffff, Z1, 2);
    const float invZ0 = 1.0f / Z0;
    const float invZ1 = 1.0f / Z1;

    float* c0 = g_ctx + (size_t)(b * Sc + qrow) * Dc + h * HDc;
    float* c1 = c0 + (size_t)8 * Dc;
#pragma unroll
    for (int nt = 0; nt < 8; nt++) {
        const int col = nt * 8 + 2 * t;
        *(float2*)(c0 + col) = make_float2(f2tf32f(ctx[nt][0] * invZ0),
                                           f2tf32f(ctx[nt][1] * invZ0));
        *(float2*)(c1 + col) = make_float2(f2tf32f(ctx[nt][2] * invZ1),
                                           f2tf32f(ctx[nt][3] * invZ1));
    }

    if (t == 0) {
        invZs[warp * 16 + g]     = invZ0;
        invZs[warp * 16 + g + 8] = invZ1;
    }
    __syncthreads();

    float* strip = attn + ((size_t)(b * Hc + h) * Sc + (size_t)qt * AT_Q) * Sc;
    for (int r = 0; r < AT_Q; r++) {
        const float iz = invZs[r];
        float* rp = strip + (size_t)r * Sc;
#pragma unroll
        for (int i = 0; i < 4; i++) {
            const int c = (tid + i * 128) * 4;
            float4 v = *(const float4*)(rp + c);
            v.x *= iz;  v.y *= iz;  v.z *= iz;  v.w *= iz;
            *(float4*)(rp + c) = v;
        }
    }
}

// ---------------------------------------------------------------------------
// kernel_launch
//   d_in: x, Wq, bq, Wk, bk, Wv, bv, Wo, bo   (all fp32)
//   d_out: [ out (B*S*D) | attention_weights (B*H*S*S) ]  fp32
// ---------------------------------------------------------------------------
extern "C" void kernel_launch(void* const* d_in, const int* in_sizes, int n_in,
                              void* d_out, int out_size)
{
    (void)in_sizes; (void)n_in; (void)out_size;
    const float* x  = (const float*)d_in[0];
    const float* Wq = (const float*)d_in[1];
    const float* bq = (const float*)d_in[2];
    const float* Wk = (const float*)d_in[3];
    const float* bk = (const float*)d_in[4];
    const float* Wv = (const float*)d_in[5];
    const float* bv = (const float*)d_in[6];
    const float* Wo = (const float*)d_in[7];
    const float* bo = (const float*)d_in[8];

    float* out  = (float*)d_out;
    float* attn = out + (size_t)Bc * Sc * Dc;

    float* gq;  cudaGetSymbolAddress((void**)&gq,  g_q);
    float* gk;  cudaGetSymbolAddress((void**)&gk,  g_k);
    float* gv;  cudaGetSymbolAddress((void**)&gv,  g_v);
    float* gc;  cudaGetSymbolAddress((void**)&gc,  g_ctx);
    float* gxr; cudaGetSymbolAddress((void**)&gxr, g_xr);
    float* gwr; cudaGetSymbolAddress((void**)&gwr, g_wr);

    const float* wq = gwr;
    const float* wk = gwr + (size_t)Dc * Dc;
    const float* wv = gwr + 2 * (size_t)Dc * Dc;
    const float* wo = gwr + 3 * (size_t)Dc * Dc;

    // One-shot RNA rounding of x and all weights
    round_inputs<<<1024, 256>>>(x, Wq, Wk, Wv, Wo);

    cudaFuncSetAttribute(gemm3_cp, cudaFuncAttributeMaxDynamicSharedMemorySize, G_SMEM);

    dim3 gemmBlock(256);

    // Q/K/V projections (rounded outputs for the attention stage)
    dim3 qkvGrid(Dc / 64, Mc / 128, 3);      // (16, 32, 3)
    gemm3_cp<<<qkvGrid, gemmBlock, G_SMEM>>>(
        gxr, wq, bq, gq, wk, bk, gk, wv, bv, gv, 1);

    // Flash attention: weights (normalized in epilogue) + rounded ctx
    dim3 attnGrid(Sc / AT_Q, Hc, Bc);        // (32, 16, 2)
    attention_flash4_kernel<<<attnGrid, 128>>>(attn);

    // Output projection (exact fp32 output)
    dim3 oGrid(Dc / 64, Mc / 128, 1);        // (16, 32, 1)
    gemm3_cp<<<oGrid, gemmBlock, G_SMEM>>>(
        gc, wo, bo, out, wo, bo, out, wo, bo, out, 0);
}